// round 8
// baseline (speedup 1.0000x reference)
#include <cuda_runtime.h>
#include <cuda_bf16.h>
#include <cstdint>
#include <cstddef>

// Problem constants
#define BATCH   4
#define T_SEQ   2048
#define CDIM    1024
#define NHEADS  16
#define HDIM    64
#define MROWS   (BATCH * T_SEQ)        // 8192
#define N_QKV   (3 * CDIM)             // 3072

// ---------------------------------------------------------------------------
// Scratch (device globals — no runtime allocation allowed)
// ---------------------------------------------------------------------------
__device__ __align__(256) __nv_bfloat16 g_xhi[(size_t)MROWS * CDIM];
__device__ __align__(256) __nv_bfloat16 g_xlo[(size_t)MROWS * CDIM];
__device__ __align__(256) __nv_bfloat16 g_qkvh[(size_t)MROWS * N_QKV];
__device__ __align__(256) __nv_bfloat16 g_qkvl[(size_t)MROWS * N_QKV];
__device__ __align__(256) __nv_bfloat16 g_yhi[(size_t)MROWS * CDIM];
__device__ __align__(256) __nv_bfloat16 g_ylo[(size_t)MROWS * CDIM];
__device__ __align__(256) __nv_bfloat16 g_wah[(size_t)N_QKV * CDIM];
__device__ __align__(256) __nv_bfloat16 g_wal[(size_t)N_QKV * CDIM];
__device__ __align__(256) __nv_bfloat16 g_wph[(size_t)CDIM * CDIM];
__device__ __align__(256) __nv_bfloat16 g_wpl[(size_t)CDIM * CDIM];

// ---------------------------------------------------------------------------
// Helpers
// ---------------------------------------------------------------------------
__device__ __forceinline__ uint32_t smem_u32(const void* p) {
    uint32_t a;
    asm("{ .reg .u64 t; cvta.to.shared.u64 t, %1; cvt.u32.u64 %0, t; }"
        : "=r"(a) : "l"(p));
    return a;
}
__device__ __forceinline__ void cp_async16(uint32_t saddr, const void* gaddr) {
    asm volatile("cp.async.ca.shared.global [%0], [%1], 16;"
                 :: "r"(saddr), "l"(gaddr));
}
__device__ __forceinline__ void cp_commit() { asm volatile("cp.async.commit_group;"); }
__device__ __forceinline__ void cp_wait1()  { asm volatile("cp.async.wait_group 1;"); }
__device__ __forceinline__ void cp_wait0()  { asm volatile("cp.async.wait_group 0;"); }

__device__ __forceinline__ void ldmatrix_x4(uint32_t* r, uint32_t addr) {
    asm volatile("ldmatrix.sync.aligned.m8n8.x4.shared.b16 {%0,%1,%2,%3}, [%4];"
                 : "=r"(r[0]), "=r"(r[1]), "=r"(r[2]), "=r"(r[3]) : "r"(addr));
}
__device__ __forceinline__ void ldmatrix_x4_trans(uint32_t* r, uint32_t addr) {
    asm volatile("ldmatrix.sync.aligned.m8n8.x4.trans.shared.b16 {%0,%1,%2,%3}, [%4];"
                 : "=r"(r[0]), "=r"(r[1]), "=r"(r[2]), "=r"(r[3]) : "r"(addr));
}
__device__ __forceinline__ void mma_bf16(float* d, const uint32_t* a,
                                         const uint32_t* b, const float* c) {
    asm volatile(
        "mma.sync.aligned.m16n8k16.row.col.f32.bf16.bf16.f32 "
        "{%0,%1,%2,%3}, {%4,%5,%6,%7}, {%8,%9}, {%10,%11,%12,%13};"
        : "=f"(d[0]), "=f"(d[1]), "=f"(d[2]), "=f"(d[3])
        : "r"(a[0]), "r"(a[1]), "r"(a[2]), "r"(a[3]),
          "r"(b[0]), "r"(b[1]),
          "f"(c[0]), "f"(c[1]), "f"(c[2]), "f"(c[3]));
}
__device__ __forceinline__ void splitpack2(float x, float y, uint32_t& hi, uint32_t& lo) {
    __nv_bfloat162 hp, lp;
    hp.x = __float2bfloat16(x); hp.y = __float2bfloat16(y);
    lp.x = __float2bfloat16(x - __bfloat162float(hp.x));
    lp.y = __float2bfloat16(y - __bfloat162float(hp.y));
    hi = *(uint32_t*)&hp; lo = *(uint32_t*)&lp;
}

// Swizzled 64B-row smem offset: row-major 64B rows, 16B chunk XOR'd by (row>>1)&3.
// For any 8 consecutive rows at a fixed logical chunk: even rows cover 4 distinct
// chunks in the low 64B half (banks 0-15), odd rows 4 distinct in the high half
// (banks 16-31) -> conflict-free ldmatrix; all addresses stay 16B-aligned.
__device__ __forceinline__ uint32_t swz64(uint32_t row, uint32_t chunkByte) {
    return row * 64u + (chunkByte ^ ((row & 6u) << 3));
}

// ---------------------------------------------------------------------------
// Split / transpose conversion kernels
// ---------------------------------------------------------------------------
__global__ void __launch_bounds__(256)
split_kernel(const float* __restrict__ in, __nv_bfloat16* __restrict__ hi,
             __nv_bfloat16* __restrict__ lo, int n4) {
    int i = blockIdx.x * 256 + threadIdx.x;
    if (i >= n4) return;
    float4 v = ((const float4*)in)[i];
    uint32_t h0, l0, h1, l1;
    splitpack2(v.x, v.y, h0, l0);
    splitpack2(v.z, v.w, h1, l1);
    uint2 hu, lu;
    hu.x = h0; hu.y = h1;
    lu.x = l0; lu.y = l1;
    ((uint2*)hi)[i] = hu;
    ((uint2*)lo)[i] = lu;
}

__global__ void __launch_bounds__(1024)
tsplit_kernel(const float* __restrict__ w, __nv_bfloat16* __restrict__ tHi,
              __nv_bfloat16* __restrict__ tLo, int K, int N) {
    __shared__ float tile[32][33];
    int n0 = blockIdx.x * 32, k0 = blockIdx.y * 32;
    int tx = threadIdx.x & 31, ty = threadIdx.x >> 5;
    tile[ty][tx] = w[(size_t)(k0 + ty) * N + n0 + tx];
    __syncthreads();
    float v = tile[tx][ty];
    __nv_bfloat16 h = __float2bfloat16(v);
    __nv_bfloat16 l = __float2bfloat16(v - __bfloat162float(h));
    size_t o = (size_t)(n0 + ty) * K + k0 + tx;
    tHi[o] = h;
    tLo[o] = l;
}

// ---------------------------------------------------------------------------
// HMMA bf16x3 GEMM: CTA 128x128, BK=32, 256 threads, warp tile 64x32.
// 3-stage cp.async pipeline, ONE __syncthreads per chunk, 2 CTAs/SM.
// Pad-free swizzled smem (64B rows).
// ---------------------------------------------------------------------------
#define GBK 32
#define PLANE_B (128 * 64)            // 8192
#define STAGE_B (4 * PLANE_B)         // 32768
#define GEMM_SMEM (3 * STAGE_B)       // 98304; x2 CTAs = 196608 <= 228KB

__global__ void __launch_bounds__(256, 2)
gemm_bf16x3(const __nv_bfloat16* __restrict__ Ah, const __nv_bfloat16* __restrict__ Al,
            const __nv_bfloat16* __restrict__ Bh, const __nv_bfloat16* __restrict__ Bl,
            float* __restrict__ C, __nv_bfloat16* __restrict__ Chi,
            __nv_bfloat16* __restrict__ Clo, int N, int K) {
    extern __shared__ char smem[];
    const uint32_t sb = smem_u32(smem);

    const int tid  = threadIdx.x;
    const int wid  = tid >> 5;
    const int lane = tid & 31;
    const int wm   = wid >> 2;
    const int wn   = wid & 3;
    const int bn = blockIdx.x, bm = blockIdx.y;

    const __nv_bfloat16* aH = Ah + (size_t)(bm * 128) * K;
    const __nv_bfloat16* aL = Al + (size_t)(bm * 128) * K;
    const __nv_bfloat16* bH = Bh + (size_t)(bn * 128) * K;
    const __nv_bfloat16* bL = Bl + (size_t)(bn * 128) * K;

    // copy mapping: 4 threads per row, 16B chunk each
    const uint32_t ldRow0 = (uint32_t)(tid >> 2);        // 0..63
    const uint32_t ldRow1 = ldRow0 + 64;
    const uint32_t ldCB   = (uint32_t)((tid & 3) * 16);  // chunk byte
    const uint32_t sOff0 = swz64(ldRow0, ldCB);
    const uint32_t sOff1 = swz64(ldRow1, ldCB);
    const int ldC8 = (tid & 3) * 8;                      // bf16 col

    // ldmatrix lane addressing (logical row + logical chunk byte)
    const uint32_t aRow = (uint32_t)(wm * 64 + (lane & 15));
    const uint32_t aKB  = (uint32_t)((lane >> 4) * 16);
    const uint32_t bRow = (uint32_t)(wn * 32 + ((lane >> 4) << 3) + (lane & 7));
    const uint32_t bKB  = (uint32_t)(((lane >> 3) & 1) * 16);

    float acc[4][4][4];
    #pragma unroll
    for (int i = 0; i < 4; i++)
        #pragma unroll
        for (int j = 0; j < 4; j++)
            #pragma unroll
            for (int q = 0; q < 4; q++) acc[i][j][q] = 0.0f;

    const int nchunks = K / GBK;

    auto loadChunk = [&](int c) {
        const uint32_t st = sb + (uint32_t)(c % 3) * STAGE_B;
        const int k0 = c * GBK;
        size_t g0 = (size_t)ldRow0 * K + k0 + ldC8;
        size_t g1 = (size_t)ldRow1 * K + k0 + ldC8;
        cp_async16(st + 0 * PLANE_B + sOff0, aH + g0);
        cp_async16(st + 0 * PLANE_B + sOff1, aH + g1);
        cp_async16(st + 1 * PLANE_B + sOff0, aL + g0);
        cp_async16(st + 1 * PLANE_B + sOff1, aL + g1);
        cp_async16(st + 2 * PLANE_B + sOff0, bH + g0);
        cp_async16(st + 2 * PLANE_B + sOff1, bH + g1);
        cp_async16(st + 3 * PLANE_B + sOff0, bL + g0);
        cp_async16(st + 3 * PLANE_B + sOff1, bL + g1);
        cp_commit();
    };

    loadChunk(0);
    loadChunk(1);

    for (int c = 0; c < nchunks; c++) {
        if (c + 1 < nchunks) cp_wait1(); else cp_wait0();
        __syncthreads();
        // Writes stage (c+2)%3 == stage (c-1)%3: all warps finished reading
        // chunk c-1 before the barrier above, so reuse is safe.
        if (c + 2 < nchunks) loadChunk(c + 2);

        const uint32_t st = sb + (uint32_t)(c % 3) * STAGE_B;

        #pragma unroll
        for (int kt = 0; kt < 2; kt++) {
            const uint32_t kb  = (uint32_t)(kt * 32) + aKB;
            const uint32_t kbB = (uint32_t)(kt * 32) + bKB;
            uint32_t ah[4][4], al[4][4];
            #pragma unroll
            for (int mt = 0; mt < 4; mt++) {
                uint32_t so = swz64(aRow + (uint32_t)(mt * 16), kb);
                ldmatrix_x4(ah[mt], st + 0 * PLANE_B + so);
                ldmatrix_x4(al[mt], st + 1 * PLANE_B + so);
            }
            uint32_t bh[2][4], bl[2][4];
            #pragma unroll
            for (int nt2 = 0; nt2 < 2; nt2++) {
                uint32_t so = swz64(bRow + (uint32_t)(nt2 * 16), kbB);
                ldmatrix_x4(bh[nt2], st + 2 * PLANE_B + so);
                ldmatrix_x4(bl[nt2], st + 3 * PLANE_B + so);
            }
            #pragma unroll
            for (int mt = 0; mt < 4; mt++) {
                #pragma unroll
                for (int nt = 0; nt < 4; nt++) {
                    const uint32_t* bhp = &bh[nt >> 1][(nt & 1) * 2];
                    const uint32_t* blp = &bl[nt >> 1][(nt & 1) * 2];
                    mma_bf16(acc[mt][nt], ah[mt], bhp, acc[mt][nt]);
                    mma_bf16(acc[mt][nt], ah[mt], blp, acc[mt][nt]);
                    mma_bf16(acc[mt][nt], al[mt], bhp, acc[mt][nt]);
                }
            }
        }
    }

    const int rBase = bm * 128 + wm * 64 + (lane >> 2);
    const int cBase = bn * 128 + wn * 32 + (lane & 3) * 2;
    if (Chi) {
        #pragma unroll
        for (int mt = 0; mt < 4; mt++) {
            #pragma unroll
            for (int nt = 0; nt < 4; nt++) {
                size_t i0 = (size_t)(rBase + mt * 16) * N + cBase + nt * 8;
                size_t i1 = i0 + (size_t)8 * N;
                uint32_t h0, l0, h1, l1;
                splitpack2(acc[mt][nt][0], acc[mt][nt][1], h0, l0);
                splitpack2(acc[mt][nt][2], acc[mt][nt][3], h1, l1);
                *(uint32_t*)(Chi + i0) = h0;
                *(uint32_t*)(Clo + i0) = l0;
                *(uint32_t*)(Chi + i1) = h1;
                *(uint32_t*)(Clo + i1) = l1;
            }
        }
    } else {
        #pragma unroll
        for (int mt = 0; mt < 4; mt++) {
            #pragma unroll
            for (int nt = 0; nt < 4; nt++) {
                float* p0 = C + (size_t)(rBase + mt * 16) * N + cBase + nt * 8;
                float* p1 = p0 + (size_t)8 * N;
                float2 v0; v0.x = acc[mt][nt][0]; v0.y = acc[mt][nt][1];
                float2 v1; v1.x = acc[mt][nt][2]; v1.y = acc[mt][nt][3];
                *(float2*)p0 = v0;
                *(float2*)p1 = v1;
            }
        }
    }
}

// ---------------------------------------------------------------------------
// HMMA flash attention (causal) — unchanged from round 4/6 (passing config).
// ---------------------------------------------------------------------------
#define FROWB 144
#define FQ_PLANE 18432
#define FKV_PLANE 9216
#define FSTAGE (4 * FKV_PLANE)
#define FLASH_SMEM (2 * FQ_PLANE + 2 * FSTAGE)

__global__ void __launch_bounds__(256, 1)
flash_hmma(const __nv_bfloat16* __restrict__ qkvh,
           const __nv_bfloat16* __restrict__ qkvl,
           __nv_bfloat16* __restrict__ yhi, __nv_bfloat16* __restrict__ ylo) {
    extern __shared__ char smem[];
    const uint32_t sb = smem_u32(smem);
    const int tid = threadIdx.x, wid = tid >> 5, lane = tid & 31;
    const int qt = blockIdx.x, h = blockIdx.y, b = blockIdx.z;
    const int q0 = qt * 128;
    const size_t rowB = (size_t)b * T_SEQ;
    const int ntiles = 2 * qt + 2;

    const uint32_t QHI = sb, QLO = sb + FQ_PLANE, STG0 = sb + 2 * FQ_PLANE;

    #pragma unroll
    for (int i = 0; i < 4; i++) {
        int slot = tid + i * 256;
        int row = slot >> 3, ch = slot & 7;
        size_t g = (rowB + q0 + row) * N_QKV + h * HDIM + ch * 8;
        uint32_t so = (uint32_t)(row * FROWB + ch * 16);
        cp_async16(QHI + so, qkvh + g);
        cp_async16(QLO + so, qkvl + g);
    }
    cp_commit();

    auto loadKV = [&](int kt, uint32_t stg) {
        const int k0 = kt * 64;
        #pragma unroll
        for (int i = 0; i < 2; i++) {
            int slot = tid + i * 256;
            int row = slot >> 3, ch = slot & 7;
            size_t g = (rowB + k0 + row) * N_QKV + h * HDIM + ch * 8;
            uint32_t so = (uint32_t)(row * FROWB + ch * 16);
            cp_async16(stg + so,                 qkvh + g + CDIM);
            cp_async16(stg + FKV_PLANE + so,     qkvl + g + CDIM);
            cp_async16(stg + 2 * FKV_PLANE + so, qkvh + g + 2 * CDIM);
            cp_async16(stg + 3 * FKV_PLANE + so, qkvl + g + 2 * CDIM);
        }
        cp_commit();
    };
    loadKV(0, STG0);
    loadKV(1, STG0 + FSTAGE);
    cp_wait1();
    __syncthreads();

    uint32_t qh[4][4], ql[4][4];
    {
        const uint32_t ro = (uint32_t)((wid * 16 + (lane & 15)) * FROWB)
                          + (uint32_t)((lane >> 4) * 16);
        #pragma unroll
        for (int ks = 0; ks < 4; ks++) {
            ldmatrix_x4(qh[ks], QHI + ro + ks * 32);
            ldmatrix_x4(ql[ks], QLO + ro + ks * 32);
        }
    }

    float o[8][4];
    #pragma unroll
    for (int nt = 0; nt < 8; nt++)
        #pragma unroll
        for (int j = 0; j < 4; j++) o[nt][j] = 0.0f;
    float m0 = -1e30f, m1 = -1e30f, l0 = 0.0f, l1 = 0.0f;

    const uint32_t kro = (uint32_t)((((lane >> 4) << 3) + (lane & 7)) * FROWB)
                       + (uint32_t)(((lane >> 3) & 1) * 16);
    const uint32_t vro = (uint32_t)((lane & 15) * FROWB)
                       + (uint32_t)(((lane >> 4) << 3) * 2);

    for (int kt = 0; kt < ntiles; kt++) {
        const uint32_t stg = STG0 + (uint32_t)(kt & 1) * FSTAGE;
        const int k0 = kt * 64;

        float s[8][4];
        #pragma unroll
        for (int nt = 0; nt < 8; nt++)
            #pragma unroll
            for (int j = 0; j < 4; j++) s[nt][j] = 0.0f;

        #pragma unroll
        for (int ks = 0; ks < 4; ks++) {
            uint32_t kh[4][4], kl[4][4];
            #pragma unroll
            for (int p4 = 0; p4 < 4; p4++) {
                uint32_t off = kro + (uint32_t)(p4 * 16 * FROWB) + (uint32_t)(ks * 32);
                ldmatrix_x4(kh[p4], stg + off);
                ldmatrix_x4(kl[p4], stg + FKV_PLANE + off);
            }
            #pragma unroll
            for (int nt = 0; nt < 8; nt++) {
                const uint32_t* bh = &kh[nt >> 1][(nt & 1) * 2];
                const uint32_t* bl = &kl[nt >> 1][(nt & 1) * 2];
                mma_bf16(s[nt], qh[ks], bh, s[nt]);
                mma_bf16(s[nt], qh[ks], bl, s[nt]);
                mma_bf16(s[nt], ql[ks], bh, s[nt]);
            }
        }

        #pragma unroll
        for (int nt = 0; nt < 8; nt++)
            #pragma unroll
            for (int j = 0; j < 4; j++) s[nt][j] *= 0.125f;

        if (kt >= ntiles - 2) {
            const int qr = q0 + wid * 16 + (lane >> 2);
            const int kc = k0 + (lane & 3) * 2;
            #pragma unroll
            for (int nt = 0; nt < 8; nt++)
                #pragma unroll
                for (int j = 0; j < 4; j++)
                    if (kc + nt * 8 + (j & 1) > qr + ((j >> 1) << 3))
                        s[nt][j] = -1e30f;
        }

        float mx0 = -1e30f, mx1 = -1e30f;
        #pragma unroll
        for (int nt = 0; nt < 8; nt++) {
            mx0 = fmaxf(mx0, fmaxf(s[nt][0], s[nt][1]));
            mx1 = fmaxf(mx1, fmaxf(s[nt][2], s[nt][3]));
        }
        mx0 = fmaxf(mx0, __shfl_xor_sync(0xFFFFFFFFu, mx0, 1));
        mx0 = fmaxf(mx0, __shfl_xor_sync(0xFFFFFFFFu, mx0, 2));
        mx1 = fmaxf(mx1, __shfl_xor_sync(0xFFFFFFFFu, mx1, 1));
        mx1 = fmaxf(mx1, __shfl_xor_sync(0xFFFFFFFFu, mx1, 2));

        const float mn0 = fmaxf(m0, mx0), mn1 = fmaxf(m1, mx1);
        const float c0 = __expf(m0 - mn0), c1 = __expf(m1 - mn1);
        m0 = mn0; m1 = mn1;

        float sum0 = 0.0f, sum1 = 0.0f;
        #pragma unroll
        for (int nt = 0; nt < 8; nt++) {
            s[nt][0] = __expf(s[nt][0] - m0); sum0 += s[nt][0];
            s[nt][1] = __expf(s[nt][1] - m0); sum0 += s[nt][1];
            s[nt][2] = __expf(s[nt][2] - m1); sum1 += s[nt][2];
            s[nt][3] = __expf(s[nt][3] - m1); sum1 += s[nt][3];
        }
        sum0 += __shfl_xor_sync(0xFFFFFFFFu, sum0, 1);
        sum0 += __shfl_xor_sync(0xFFFFFFFFu, sum0, 2);
        sum1 += __shfl_xor_sync(0xFFFFFFFFu, sum1, 1);
        sum1 += __shfl_xor_sync(0xFFFFFFFFu, sum1, 2);
        l0 = l0 * c0 + sum0;
        l1 = l1 * c1 + sum1;

        #pragma unroll
        for (int nt = 0; nt < 8; nt++) {
            o[nt][0] *= c0; o[nt][1] *= c0;
            o[nt][2] *= c1; o[nt][3] *= c1;
        }

        #pragma unroll
        for (int ks = 0; ks < 4; ks++) {
            uint32_t pah[4], pal[4];
            splitpack2(s[2 * ks][0],     s[2 * ks][1],     pah[0], pal[0]);
            splitpack2(s[2 * ks][2],     s[2 * ks][3],     pah[1], pal[1]);
            splitpack2(s[2 * ks + 1][0], s[2 * ks + 1][1], pah[2], pal[2]);
            splitpack2(s[2 * ks + 1][2], s[2 * ks + 1][3], pah[3], pal[3]);

            uint32_t vh[4][4], vl[4][4];
            #pragma unroll
            for (int p4 = 0; p4 < 4; p4++) {
                uint32_t off = vro + (uint32_t)(ks * 16 * FROWB) + (uint32_t)(p4 * 32);
                ldmatrix_x4_trans(vh[p4], stg + 2 * FKV_PLANE + off);
                ldmatrix_x4_trans(vl[p4], stg + 3 * FKV_PLANE + off);
            }
            #pragma unroll
            for (int nt = 0; nt < 8; nt++) {
                const uint32_t* bh = &vh[nt >> 1][(nt & 1) * 2];
                const uint32_t* bl = &vl[nt >> 1][(nt & 1) * 2];
                mma_bf16(o[nt], pah, bh, o[nt]);
                mma_bf16(o[nt], pal, bh, o[nt]);
                mma_bf16(o[nt], pah, bl, o[nt]);
            }
        }

        __syncthreads();
        if (kt + 2 < ntiles) loadKV(kt + 2, stg);
        if (kt + 1 < ntiles) {
            if (kt + 2 < ntiles) cp_wait1(); else cp_wait0();
            __syncthreads();
        }
    }

    const float inv0 = 1.0f / l0, inv1 = 1.0f / l1;
    const int row0 = q0 + wid * 16 + (lane >> 2);
    #pragma unroll
    for (int nt = 0; nt < 8; nt++) {
        const int col = h * HDIM + nt * 8 + (lane & 3) * 2;
        size_t i0 = (rowB + row0) * CDIM + col;
        size_t i1 = (rowB + row0 + 8) * CDIM + col;
        uint32_t h0, lw0, h1, lw1;
        splitpack2(o[nt][0] * inv0, o[nt][1] * inv0, h0, lw0);
        splitpack2(o[nt][2] * inv1, o[nt][3] * inv1, h1, lw1);
        *(uint32_t*)(yhi + i0) = h0;
        *(uint32_t*)(ylo + i0) = lw0;
        *(uint32_t*)(yhi + i1) = h1;
        *(uint32_t*)(ylo + i1) = lw1;
    }
}

// ---------------------------------------------------------------------------
// Launch
// ---------------------------------------------------------------------------
extern "C" void kernel_launch(void* const* d_in, const int* in_sizes, int n_in,
                              void* d_out, int out_size) {
    (void)in_sizes; (void)n_in; (void)out_size;
    const float* x      = (const float*)d_in[0];
    const float* w_attn = (const float*)d_in[1];
    const float* w_proj = (const float*)d_in[2];
    float* out = (float*)d_out;

    __nv_bfloat16 *xhi, *xlo, *qkvh, *qkvl, *yhi, *ylo, *wah, *wal, *wph, *wpl;
    cudaGetSymbolAddress((void**)&xhi,  g_xhi);
    cudaGetSymbolAddress((void**)&xlo,  g_xlo);
    cudaGetSymbolAddress((void**)&qkvh, g_qkvh);
    cudaGetSymbolAddress((void**)&qkvl, g_qkvl);
    cudaGetSymbolAddress((void**)&yhi,  g_yhi);
    cudaGetSymbolAddress((void**)&ylo,  g_ylo);
    cudaGetSymbolAddress((void**)&wah,  g_wah);
    cudaGetSymbolAddress((void**)&wal,  g_wal);
    cudaGetSymbolAddress((void**)&wph,  g_wph);
    cudaGetSymbolAddress((void**)&wpl,  g_wpl);

    cudaFuncSetAttribute(gemm_bf16x3, cudaFuncAttributeMaxDynamicSharedMemorySize, GEMM_SMEM);
    cudaFuncSetAttribute(flash_hmma,  cudaFuncAttributeMaxDynamicSharedMemorySize, FLASH_SMEM);

    {
        int n4 = MROWS * CDIM / 4;
        split_kernel<<<(n4 + 255) / 256, 256>>>(x, xhi, xlo, n4);
        tsplit_kernel<<<dim3(N_QKV / 32, CDIM / 32), 1024>>>(w_attn, wah, wal, CDIM, N_QKV);
        tsplit_kernel<<<dim3(CDIM / 32, CDIM / 32), 1024>>>(w_proj, wph, wpl, CDIM, CDIM);
    }
    // 1) qkv = x @ w_attn -> bf16 hi/lo
    gemm_bf16x3<<<dim3(N_QKV / 128, MROWS / 128), 256, GEMM_SMEM>>>(
        xhi, xlo, wah, wal, nullptr, qkvh, qkvl, N_QKV, CDIM);
    // 2) attention
    flash_hmma<<<dim3(T_SEQ / 128, NHEADS, BATCH), 256, FLASH_SMEM>>>(
        qkvh, qkvl, yhi, ylo);
    // 3) out = y @ w_proj (fp32)
    gemm_bf16x3<<<dim3(CDIM / 128, MROWS / 128), 256, GEMM_SMEM>>>(
        yhi, ylo, wph, wpl, out, nullptr, nullptr, CDIM, CDIM);
}

// round 9
// speedup vs baseline: 1.3488x; 1.3488x over previous
#include <cuda_runtime.h>
#include <cuda_bf16.h>
#include <cuda_fp16.h>
#include <cstdint>
#include <cstddef>

// Problem constants
#define BATCH   4
#define T_SEQ   2048
#define CDIM    1024
#define NHEADS  16
#define HDIM    64
#define MROWS   (BATCH * T_SEQ)        // 8192
#define N_QKV   (3 * CDIM)             // 3072

// ---------------------------------------------------------------------------
// Scratch (device globals — no runtime allocation allowed)
// ---------------------------------------------------------------------------
__device__ __align__(256) __half         g_xh [(size_t)MROWS * CDIM];
__device__ __align__(256) __nv_bfloat16  g_qkvh[(size_t)MROWS * N_QKV];
__device__ __align__(256) __nv_bfloat16  g_qkvl[(size_t)MROWS * N_QKV];
__device__ __align__(256) __half         g_yh [(size_t)MROWS * CDIM];
__device__ __align__(256) __half         g_wah[(size_t)N_QKV * CDIM];
__device__ __align__(256) __half         g_wal[(size_t)N_QKV * CDIM];
__device__ __align__(256) __half         g_wph[(size_t)CDIM * CDIM];
__device__ __align__(256) __half         g_wpl[(size_t)CDIM * CDIM];

// ---------------------------------------------------------------------------
// Helpers
// ---------------------------------------------------------------------------
__device__ __forceinline__ uint32_t smem_u32(const void* p) {
    uint32_t a;
    asm("{ .reg .u64 t; cvta.to.shared.u64 t, %1; cvt.u32.u64 %0, t; }"
        : "=r"(a) : "l"(p));
    return a;
}
__device__ __forceinline__ void cp_async16(uint32_t saddr, const void* gaddr) {
    asm volatile("cp.async.ca.shared.global [%0], [%1], 16;"
                 :: "r"(saddr), "l"(gaddr));
}
__device__ __forceinline__ void cp_commit() { asm volatile("cp.async.commit_group;"); }
__device__ __forceinline__ void cp_wait1()  { asm volatile("cp.async.wait_group 1;"); }
__device__ __forceinline__ void cp_wait0()  { asm volatile("cp.async.wait_group 0;"); }

__device__ __forceinline__ void ldmatrix_x4(uint32_t* r, uint32_t addr) {
    asm volatile("ldmatrix.sync.aligned.m8n8.x4.shared.b16 {%0,%1,%2,%3}, [%4];"
                 : "=r"(r[0]), "=r"(r[1]), "=r"(r[2]), "=r"(r[3]) : "r"(addr));
}
__device__ __forceinline__ void ldmatrix_x4_trans(uint32_t* r, uint32_t addr) {
    asm volatile("ldmatrix.sync.aligned.m8n8.x4.trans.shared.b16 {%0,%1,%2,%3}, [%4];"
                 : "=r"(r[0]), "=r"(r[1]), "=r"(r[2]), "=r"(r[3]) : "r"(addr));
}
__device__ __forceinline__ void mma_bf16(float* d, const uint32_t* a,
                                         const uint32_t* b, const float* c) {
    asm volatile(
        "mma.sync.aligned.m16n8k16.row.col.f32.bf16.bf16.f32 "
        "{%0,%1,%2,%3}, {%4,%5,%6,%7}, {%8,%9}, {%10,%11,%12,%13};"
        : "=f"(d[0]), "=f"(d[1]), "=f"(d[2]), "=f"(d[3])
        : "r"(a[0]), "r"(a[1]), "r"(a[2]), "r"(a[3]),
          "r"(b[0]), "r"(b[1]),
          "f"(c[0]), "f"(c[1]), "f"(c[2]), "f"(c[3]));
}
__device__ __forceinline__ void mma_f16(float* d, const uint32_t* a,
                                        const uint32_t* b, const float* c) {
    asm volatile(
        "mma.sync.aligned.m16n8k16.row.col.f32.f16.f16.f32 "
        "{%0,%1,%2,%3}, {%4,%5,%6,%7}, {%8,%9}, {%10,%11,%12,%13};"
        : "=f"(d[0]), "=f"(d[1]), "=f"(d[2]), "=f"(d[3])
        : "r"(a[0]), "r"(a[1]), "r"(a[2]), "r"(a[3]),
          "r"(b[0]), "r"(b[1]),
          "f"(c[0]), "f"(c[1]), "f"(c[2]), "f"(c[3]));
}
__device__ __forceinline__ void splitpack2(float x, float y, uint32_t& hi, uint32_t& lo) {
    __nv_bfloat162 hp, lp;
    hp.x = __float2bfloat16(x); hp.y = __float2bfloat16(y);
    lp.x = __float2bfloat16(x - __bfloat162float(hp.x));
    lp.y = __float2bfloat16(y - __bfloat162float(hp.y));
    hi = *(uint32_t*)&hp; lo = *(uint32_t*)&lp;
}
__device__ __forceinline__ uint32_t packh2(float x, float y) {
    __half2 p;
    p.x = __float2half_rn(x); p.y = __float2half_rn(y);
    return *(uint32_t*)&p;
}

// ---------------------------------------------------------------------------
// Conversion kernels
// ---------------------------------------------------------------------------
__global__ void __launch_bounds__(256)
xcvt_kernel(const float* __restrict__ in, __half* __restrict__ outH, int n4) {
    int i = blockIdx.x * 256 + threadIdx.x;
    if (i >= n4) return;
    float4 v = ((const float4*)in)[i];
    uint2 o;
    o.x = packh2(v.x, v.y);
    o.y = packh2(v.z, v.w);
    ((uint2*)outH)[i] = o;
}

// Transpose + fp16 hi/lo split: w[K,N] fp32 -> wT hi/lo [N,K] half
__global__ void __launch_bounds__(1024)
tsplit16_kernel(const float* __restrict__ w, __half* __restrict__ tHi,
                __half* __restrict__ tLo, int K, int N) {
    __shared__ float tile[32][33];
    int n0 = blockIdx.x * 32, k0 = blockIdx.y * 32;
    int tx = threadIdx.x & 31, ty = threadIdx.x >> 5;
    tile[ty][tx] = w[(size_t)(k0 + ty) * N + n0 + tx];
    __syncthreads();
    float v = tile[tx][ty];
    __half h = __float2half_rn(v);
    __half l = __float2half_rn(v - __half2float(h));
    size_t o = (size_t)(n0 + ty) * K + k0 + tx;
    tHi[o] = h;
    tLo[o] = l;
}

// ---------------------------------------------------------------------------
// HMMA fp16x2 GEMM: C = Ah[M,K] * (Bh+Bl)^T[N,K]   (activation lo-plane dropped)
// CTA 128x128, BK=32, 256 threads, warp tile 64x32, 2-stage cp.async,
// 2 CTAs/SM, padded 80B rows (round-6 proven structure, 3 planes).
// ---------------------------------------------------------------------------
#define GBK 32
#define ROWB 80
#define PLANE_B (128 * ROWB)          // 10240
#define STAGE_B (3 * PLANE_B)         // 30720
#define GEMM_SMEM (2 * STAGE_B)       // 61440; x2 CTAs = 122880 <= 228KB

__global__ void __launch_bounds__(256, 2)
gemm_f16x2(const __half* __restrict__ Ah, const __half* __restrict__ Bh,
           const __half* __restrict__ Bl, float* __restrict__ C,
           __nv_bfloat16* __restrict__ Chi, __nv_bfloat16* __restrict__ Clo,
           int N, int K) {
    extern __shared__ char smem[];
    const uint32_t sb = smem_u32(smem);

    const int tid  = threadIdx.x;
    const int wid  = tid >> 5;
    const int lane = tid & 31;
    const int wm   = wid >> 2;
    const int wn   = wid & 3;
    const int bn = blockIdx.x, bm = blockIdx.y;

    const __half* aH = Ah + (size_t)(bm * 128) * K;
    const __half* bH = Bh + (size_t)(bn * 128) * K;
    const __half* bL = Bl + (size_t)(bn * 128) * K;

    const int ldRow0 = tid >> 2;
    const int ldRow1 = ldRow0 + 64;
    const int ldC8   = (tid & 3) * 8;
    const uint32_t sOff0 = (uint32_t)(ldRow0 * ROWB + ldC8 * 2);
    const uint32_t sOff1 = (uint32_t)(ldRow1 * ROWB + ldC8 * 2);

    const int aRow = wm * 64 + (lane & 15);
    const uint32_t aKB = (uint32_t)((lane >> 4) * 16);
    const int bRow = wn * 32 + ((lane >> 4) << 3) + (lane & 7);
    const uint32_t bKB = (uint32_t)(((lane >> 3) & 1) * 16);

    float acc[4][4][4];
    #pragma unroll
    for (int i = 0; i < 4; i++)
        #pragma unroll
        for (int j = 0; j < 4; j++)
            #pragma unroll
            for (int q = 0; q < 4; q++) acc[i][j][q] = 0.0f;

    const int nchunks = K / GBK;

    {
        size_t g0 = (size_t)ldRow0 * K + ldC8;
        size_t g1 = (size_t)ldRow1 * K + ldC8;
        cp_async16(sb + 0 * PLANE_B + sOff0, aH + g0);
        cp_async16(sb + 0 * PLANE_B + sOff1, aH + g1);
        cp_async16(sb + 1 * PLANE_B + sOff0, bH + g0);
        cp_async16(sb + 1 * PLANE_B + sOff1, bH + g1);
        cp_async16(sb + 2 * PLANE_B + sOff0, bL + g0);
        cp_async16(sb + 2 * PLANE_B + sOff1, bL + g1);
        cp_commit();
    }

    for (int c = 0; c < nchunks; c++) {
        const uint32_t st = sb + (uint32_t)(c & 1) * STAGE_B;
        if (c + 1 < nchunks) {
            const uint32_t st2 = sb + (uint32_t)((c + 1) & 1) * STAGE_B;
            const int k0 = (c + 1) * GBK;
            size_t g0 = (size_t)ldRow0 * K + k0 + ldC8;
            size_t g1 = (size_t)ldRow1 * K + k0 + ldC8;
            cp_async16(st2 + 0 * PLANE_B + sOff0, aH + g0);
            cp_async16(st2 + 0 * PLANE_B + sOff1, aH + g1);
            cp_async16(st2 + 1 * PLANE_B + sOff0, bH + g0);
            cp_async16(st2 + 1 * PLANE_B + sOff1, bH + g1);
            cp_async16(st2 + 2 * PLANE_B + sOff0, bL + g0);
            cp_async16(st2 + 2 * PLANE_B + sOff1, bL + g1);
            cp_commit();
            cp_wait1();
        } else {
            cp_wait0();
        }
        __syncthreads();

        #pragma unroll
        for (int kt = 0; kt < 2; kt++) {
            const uint32_t kb  = (uint32_t)(kt * 32) + aKB;
            const uint32_t kbB = (uint32_t)(kt * 32) + bKB;
            uint32_t ah[4][4];
            #pragma unroll
            for (int mt = 0; mt < 4; mt++) {
                uint32_t ro = (uint32_t)((aRow + mt * 16) * ROWB);
                ldmatrix_x4(ah[mt], st + 0 * PLANE_B + ro + kb);
            }
            uint32_t bh[2][4], bl[2][4];
            #pragma unroll
            for (int nt2 = 0; nt2 < 2; nt2++) {
                uint32_t ro = (uint32_t)((bRow + nt2 * 16) * ROWB);
                ldmatrix_x4(bh[nt2], st + 1 * PLANE_B + ro + kbB);
                ldmatrix_x4(bl[nt2], st + 2 * PLANE_B + ro + kbB);
            }
            #pragma unroll
            for (int mt = 0; mt < 4; mt++) {
                #pragma unroll
                for (int nt = 0; nt < 4; nt++) {
                    const uint32_t* bhp = &bh[nt >> 1][(nt & 1) * 2];
                    const uint32_t* blp = &bl[nt >> 1][(nt & 1) * 2];
                    mma_f16(acc[mt][nt], ah[mt], bhp, acc[mt][nt]);
                    mma_f16(acc[mt][nt], ah[mt], blp, acc[mt][nt]);
                }
            }
        }
        __syncthreads();
    }

    const int rBase = bm * 128 + wm * 64 + (lane >> 2);
    const int cBase = bn * 128 + wn * 32 + (lane & 3) * 2;
    if (Chi) {
        #pragma unroll
        for (int mt = 0; mt < 4; mt++) {
            #pragma unroll
            for (int nt = 0; nt < 4; nt++) {
                size_t i0 = (size_t)(rBase + mt * 16) * N + cBase + nt * 8;
                size_t i1 = i0 + (size_t)8 * N;
                uint32_t h0, l0, h1, l1;
                splitpack2(acc[mt][nt][0], acc[mt][nt][1], h0, l0);
                splitpack2(acc[mt][nt][2], acc[mt][nt][3], h1, l1);
                *(uint32_t*)(Chi + i0) = h0;
                *(uint32_t*)(Clo + i0) = l0;
                *(uint32_t*)(Chi + i1) = h1;
                *(uint32_t*)(Clo + i1) = l1;
            }
        }
    } else {
        #pragma unroll
        for (int mt = 0; mt < 4; mt++) {
            #pragma unroll
            for (int nt = 0; nt < 4; nt++) {
                float* p0 = C + (size_t)(rBase + mt * 16) * N + cBase + nt * 8;
                float* p1 = p0 + (size_t)8 * N;
                float2 v0; v0.x = acc[mt][nt][0]; v0.y = acc[mt][nt][1];
                float2 v1; v1.x = acc[mt][nt][2]; v1.y = acc[mt][nt][3];
                *(float2*)p0 = v0;
                *(float2*)p1 = v1;
            }
        }
    }
}

// ---------------------------------------------------------------------------
// HMMA flash attention (causal), bf16x3 — unchanged math from round 6;
// epilogue now writes a single fp16 y plane (proj drops the y lo-plane).
// ---------------------------------------------------------------------------
#define FROWB 144
#define FQ_PLANE 18432
#define FKV_PLANE 9216
#define FSTAGE (4 * FKV_PLANE)
#define FLASH_SMEM (2 * FQ_PLANE + 2 * FSTAGE)

__global__ void __launch_bounds__(256, 1)
flash_hmma(const __nv_bfloat16* __restrict__ qkvh,
           const __nv_bfloat16* __restrict__ qkvl,
           __half* __restrict__ yh) {
    extern __shared__ char smem[];
    const uint32_t sb = smem_u32(smem);
    const int tid = threadIdx.x, wid = tid >> 5, lane = tid & 31;
    const int qt = blockIdx.x, h = blockIdx.y, b = blockIdx.z;
    const int q0 = qt * 128;
    const size_t rowB = (size_t)b * T_SEQ;
    const int ntiles = 2 * qt + 2;

    const uint32_t QHI = sb, QLO = sb + FQ_PLANE, STG0 = sb + 2 * FQ_PLANE;

    #pragma unroll
    for (int i = 0; i < 4; i++) {
        int slot = tid + i * 256;
        int row = slot >> 3, ch = slot & 7;
        size_t g = (rowB + q0 + row) * N_QKV + h * HDIM + ch * 8;
        uint32_t so = (uint32_t)(row * FROWB + ch * 16);
        cp_async16(QHI + so, qkvh + g);
        cp_async16(QLO + so, qkvl + g);
    }
    cp_commit();

    auto loadKV = [&](int kt, uint32_t stg) {
        const int k0 = kt * 64;
        #pragma unroll
        for (int i = 0; i < 2; i++) {
            int slot = tid + i * 256;
            int row = slot >> 3, ch = slot & 7;
            size_t g = (rowB + k0 + row) * N_QKV + h * HDIM + ch * 8;
            uint32_t so = (uint32_t)(row * FROWB + ch * 16);
            cp_async16(stg + so,                 qkvh + g + CDIM);
            cp_async16(stg + FKV_PLANE + so,     qkvl + g + CDIM);
            cp_async16(stg + 2 * FKV_PLANE + so, qkvh + g + 2 * CDIM);
            cp_async16(stg + 3 * FKV_PLANE + so, qkvl + g + 2 * CDIM);
        }
        cp_commit();
    };
    loadKV(0, STG0);
    loadKV(1, STG0 + FSTAGE);
    cp_wait1();
    __syncthreads();

    uint32_t qh[4][4], ql[4][4];
    {
        const uint32_t ro = (uint32_t)((wid * 16 + (lane & 15)) * FROWB)
                          + (uint32_t)((lane >> 4) * 16);
        #pragma unroll
        for (int ks = 0; ks < 4; ks++) {
            ldmatrix_x4(qh[ks], QHI + ro + ks * 32);
            ldmatrix_x4(ql[ks], QLO + ro + ks * 32);
        }
    }

    float o[8][4];
    #pragma unroll
    for (int nt = 0; nt < 8; nt++)
        #pragma unroll
        for (int j = 0; j < 4; j++) o[nt][j] = 0.0f;
    float m0 = -1e30f, m1 = -1e30f, l0 = 0.0f, l1 = 0.0f;

    const uint32_t kro = (uint32_t)((((lane >> 4) << 3) + (lane & 7)) * FROWB)
                       + (uint32_t)(((lane >> 3) & 1) * 16);
    const uint32_t vro = (uint32_t)((lane & 15) * FROWB)
                       + (uint32_t)(((lane >> 4) << 3) * 2);

    for (int kt = 0; kt < ntiles; kt++) {
        const uint32_t stg = STG0 + (uint32_t)(kt & 1) * FSTAGE;
        const int k0 = kt * 64;

        float s[8][4];
        #pragma unroll
        for (int nt = 0; nt < 8; nt++)
            #pragma unroll
            for (int j = 0; j < 4; j++) s[nt][j] = 0.0f;

        #pragma unroll
        for (int ks = 0; ks < 4; ks++) {
            uint32_t kh[4][4], kl[4][4];
            #pragma unroll
            for (int p4 = 0; p4 < 4; p4++) {
                uint32_t off = kro + (uint32_t)(p4 * 16 * FROWB) + (uint32_t)(ks * 32);
                ldmatrix_x4(kh[p4], stg + off);
                ldmatrix_x4(kl[p4], stg + FKV_PLANE + off);
            }
            #pragma unroll
            for (int nt = 0; nt < 8; nt++) {
                const uint32_t* bh = &kh[nt >> 1][(nt & 1) * 2];
                const uint32_t* bl = &kl[nt >> 1][(nt & 1) * 2];
                mma_bf16(s[nt], qh[ks], bh, s[nt]);
                mma_bf16(s[nt], qh[ks], bl, s[nt]);
                mma_bf16(s[nt], ql[ks], bh, s[nt]);
            }
        }

        #pragma unroll
        for (int nt = 0; nt < 8; nt++)
            #pragma unroll
            for (int j = 0; j < 4; j++) s[nt][j] *= 0.125f;

        if (kt >= ntiles - 2) {
            const int qr = q0 + wid * 16 + (lane >> 2);
            const int kc = k0 + (lane & 3) * 2;
            #pragma unroll
            for (int nt = 0; nt < 8; nt++)
                #pragma unroll
                for (int j = 0; j < 4; j++)
                    if (kc + nt * 8 + (j & 1) > qr + ((j >> 1) << 3))
                        s[nt][j] = -1e30f;
        }

        float mx0 = -1e30f, mx1 = -1e30f;
        #pragma unroll
        for (int nt = 0; nt < 8; nt++) {
            mx0 = fmaxf(mx0, fmaxf(s[nt][0], s[nt][1]));
            mx1 = fmaxf(mx1, fmaxf(s[nt][2], s[nt][3]));
        }
        mx0 = fmaxf(mx0, __shfl_xor_sync(0xFFFFFFFFu, mx0, 1));
        mx0 = fmaxf(mx0, __shfl_xor_sync(0xFFFFFFFFu, mx0, 2));
        mx1 = fmaxf(mx1, __shfl_xor_sync(0xFFFFFFFFu, mx1, 1));
        mx1 = fmaxf(mx1, __shfl_xor_sync(0xFFFFFFFFu, mx1, 2));

        const float mn0 = fmaxf(m0, mx0), mn1 = fmaxf(m1, mx1);
        const float c0 = __expf(m0 - mn0), c1 = __expf(m1 - mn1);
        m0 = mn0; m1 = mn1;

        float sum0 = 0.0f, sum1 = 0.0f;
        #pragma unroll
        for (int nt = 0; nt < 8; nt++) {
            s[nt][0] = __expf(s[nt][0] - m0); sum0 += s[nt][0];
            s[nt][1] = __expf(s[nt][1] - m0); sum0 += s[nt][1];
            s[nt][2] = __expf(s[nt][2] - m1); sum1 += s[nt][2];
            s[nt][3] = __expf(s[nt][3] - m1); sum1 += s[nt][3];
        }
        sum0 += __shfl_xor_sync(0xFFFFFFFFu, sum0, 1);
        sum0 += __shfl_xor_sync(0xFFFFFFFFu, sum0, 2);
        sum1 += __shfl_xor_sync(0xFFFFFFFFu, sum1, 1);
        sum1 += __shfl_xor_sync(0xFFFFFFFFu, sum1, 2);
        l0 = l0 * c0 + sum0;
        l1 = l1 * c1 + sum1;

        #pragma unroll
        for (int nt = 0; nt < 8; nt++) {
            o[nt][0] *= c0; o[nt][1] *= c0;
            o[nt][2] *= c1; o[nt][3] *= c1;
        }

        #pragma unroll
        for (int ks = 0; ks < 4; ks++) {
            uint32_t pah[4], pal[4];
            splitpack2(s[2 * ks][0],     s[2 * ks][1],     pah[0], pal[0]);
            splitpack2(s[2 * ks][2],     s[2 * ks][3],     pah[1], pal[1]);
            splitpack2(s[2 * ks + 1][0], s[2 * ks + 1][1], pah[2], pal[2]);
            splitpack2(s[2 * ks + 1][2], s[2 * ks + 1][3], pah[3], pal[3]);

            uint32_t vh[4][4], vl[4][4];
            #pragma unroll
            for (int p4 = 0; p4 < 4; p4++) {
                uint32_t off = vro + (uint32_t)(ks * 16 * FROWB) + (uint32_t)(p4 * 32);
                ldmatrix_x4_trans(vh[p4], stg + 2 * FKV_PLANE + off);
                ldmatrix_x4_trans(vl[p4], stg + 3 * FKV_PLANE + off);
            }
            #pragma unroll
            for (int nt = 0; nt < 8; nt++) {
                const uint32_t* bh = &vh[nt >> 1][(nt & 1) * 2];
                const uint32_t* bl = &vl[nt >> 1][(nt & 1) * 2];
                mma_bf16(o[nt], pah, bh, o[nt]);
                mma_bf16(o[nt], pal, bh, o[nt]);
                mma_bf16(o[nt], pah, bl, o[nt]);
            }
        }

        __syncthreads();
        if (kt + 2 < ntiles) loadKV(kt + 2, stg);
        if (kt + 1 < ntiles) {
            if (kt + 2 < ntiles) cp_wait1(); else cp_wait0();
            __syncthreads();
        }
    }

    const float inv0 = 1.0f / l0, inv1 = 1.0f / l1;
    const int row0 = q0 + wid * 16 + (lane >> 2);
    #pragma unroll
    for (int nt = 0; nt < 8; nt++) {
        const int col = h * HDIM + nt * 8 + (lane & 3) * 2;
        size_t i0 = (rowB + row0) * CDIM + col;
        size_t i1 = (rowB + row0 + 8) * CDIM + col;
        *(uint32_t*)(yh + i0) = packh2(o[nt][0] * inv0, o[nt][1] * inv0);
        *(uint32_t*)(yh + i1) = packh2(o[nt][2] * inv1, o[nt][3] * inv1);
    }
}

// ---------------------------------------------------------------------------
// Launch
// ---------------------------------------------------------------------------
extern "C" void kernel_launch(void* const* d_in, const int* in_sizes, int n_in,
                              void* d_out, int out_size) {
    (void)in_sizes; (void)n_in; (void)out_size;
    const float* x      = (const float*)d_in[0];
    const float* w_attn = (const float*)d_in[1];
    const float* w_proj = (const float*)d_in[2];
    float* out = (float*)d_out;

    __half *xh, *yh, *wah, *wal, *wph, *wpl;
    __nv_bfloat16 *qkvh, *qkvl;
    cudaGetSymbolAddress((void**)&xh,   g_xh);
    cudaGetSymbolAddress((void**)&qkvh, g_qkvh);
    cudaGetSymbolAddress((void**)&qkvl, g_qkvl);
    cudaGetSymbolAddress((void**)&yh,   g_yh);
    cudaGetSymbolAddress((void**)&wah,  g_wah);
    cudaGetSymbolAddress((void**)&wal,  g_wal);
    cudaGetSymbolAddress((void**)&wph,  g_wph);
    cudaGetSymbolAddress((void**)&wpl,  g_wpl);

    cudaFuncSetAttribute(gemm_f16x2, cudaFuncAttributeMaxDynamicSharedMemorySize, GEMM_SMEM);
    cudaFuncSetAttribute(flash_hmma, cudaFuncAttributeMaxDynamicSharedMemorySize, FLASH_SMEM);

    {
        int n4 = MROWS * CDIM / 4;
        xcvt_kernel<<<(n4 + 255) / 256, 256>>>(x, xh, n4);
        tsplit16_kernel<<<dim3(N_QKV / 32, CDIM / 32), 1024>>>(w_attn, wah, wal, CDIM, N_QKV);
        tsplit16_kernel<<<dim3(CDIM / 32, CDIM / 32), 1024>>>(w_proj, wph, wpl, CDIM, CDIM);
    }
    // 1) qkv = x @ w_attn  (fp16x2) -> bf16 hi/lo planes for flash
    gemm_f16x2<<<dim3(N_QKV / 128, MROWS / 128), 256, GEMM_SMEM>>>(
        xh, wah, wal, nullptr, qkvh, qkvl, N_QKV, CDIM);
    // 2) attention (bf16x3) -> single fp16 y plane
    flash_hmma<<<dim3(T_SEQ / 128, NHEADS, BATCH), 256, FLASH_SMEM>>>(
        qkvh, qkvl, yh);
    // 3) out = y @ w_proj  (fp16x2, fp32 out)
    gemm_f16x2<<<dim3(CDIM / 128, MROWS / 128), 256, GEMM_SMEM>>>(
        yh, wph, wpl, out, nullptr, nullptr, CDIM, CDIM);
}

// round 10
// speedup vs baseline: 1.4787x; 1.0963x over previous
#include <cuda_runtime.h>
#include <cuda_bf16.h>
#include <cuda_fp16.h>
#include <cstdint>
#include <cstddef>

// Problem constants
#define BATCH   4
#define T_SEQ   2048
#define CDIM    1024
#define NHEADS  16
#define HDIM    64
#define MROWS   (BATCH * T_SEQ)        // 8192
#define N_QKV   (3 * CDIM)             // 3072

// ---------------------------------------------------------------------------
// Scratch (device globals — no runtime allocation allowed)
// ---------------------------------------------------------------------------
__device__ __align__(256) __half g_xh  [(size_t)MROWS * CDIM];
__device__ __align__(256) __half g_qkvh[(size_t)MROWS * N_QKV];
__device__ __align__(256) __half g_qkvl[(size_t)MROWS * N_QKV];
__device__ __align__(256) __half g_yh  [(size_t)MROWS * CDIM];
__device__ __align__(256) __half g_wah [(size_t)N_QKV * CDIM];
__device__ __align__(256) __half g_wal [(size_t)N_QKV * CDIM];
__device__ __align__(256) __half g_wph [(size_t)CDIM * CDIM];
__device__ __align__(256) __half g_wpl [(size_t)CDIM * CDIM];

// ---------------------------------------------------------------------------
// Helpers
// ---------------------------------------------------------------------------
__device__ __forceinline__ uint32_t smem_u32(const void* p) {
    uint32_t a;
    asm("{ .reg .u64 t; cvta.to.shared.u64 t, %1; cvt.u32.u64 %0, t; }"
        : "=r"(a) : "l"(p));
    return a;
}
__device__ __forceinline__ void cp_async16(uint32_t saddr, const void* gaddr) {
    asm volatile("cp.async.ca.shared.global [%0], [%1], 16;"
                 :: "r"(saddr), "l"(gaddr));
}
__device__ __forceinline__ void cp_commit() { asm volatile("cp.async.commit_group;"); }
__device__ __forceinline__ void cp_wait1()  { asm volatile("cp.async.wait_group 1;"); }
__device__ __forceinline__ void cp_wait0()  { asm volatile("cp.async.wait_group 0;"); }

__device__ __forceinline__ void ldmatrix_x4(uint32_t* r, uint32_t addr) {
    asm volatile("ldmatrix.sync.aligned.m8n8.x4.shared.b16 {%0,%1,%2,%3}, [%4];"
                 : "=r"(r[0]), "=r"(r[1]), "=r"(r[2]), "=r"(r[3]) : "r"(addr));
}
__device__ __forceinline__ void ldmatrix_x4_trans(uint32_t* r, uint32_t addr) {
    asm volatile("ldmatrix.sync.aligned.m8n8.x4.trans.shared.b16 {%0,%1,%2,%3}, [%4];"
                 : "=r"(r[0]), "=r"(r[1]), "=r"(r[2]), "=r"(r[3]) : "r"(addr));
}
__device__ __forceinline__ void mma_f16(float* d, const uint32_t* a,
                                        const uint32_t* b, const float* c) {
    asm volatile(
        "mma.sync.aligned.m16n8k16.row.col.f32.f16.f16.f32 "
        "{%0,%1,%2,%3}, {%4,%5,%6,%7}, {%8,%9}, {%10,%11,%12,%13};"
        : "=f"(d[0]), "=f"(d[1]), "=f"(d[2]), "=f"(d[3])
        : "r"(a[0]), "r"(a[1]), "r"(a[2]), "r"(a[3]),
          "r"(b[0]), "r"(b[1]),
          "f"(c[0]), "f"(c[1]), "f"(c[2]), "f"(c[3]));
}
__device__ __forceinline__ uint32_t packh2(float x, float y) {
    __half2 p;
    p.x = __float2half_rn(x); p.y = __float2half_rn(y);
    return *(uint32_t*)&p;
}
__device__ __forceinline__ void splitpack2h(float x, float y, uint32_t& hi, uint32_t& lo) {
    __half2 hp, lp;
    hp.x = __float2half_rn(x); hp.y = __float2half_rn(y);
    lp.x = __float2half_rn(x - __half2float(hp.x));
    lp.y = __float2half_rn(y - __half2float(hp.y));
    hi = *(uint32_t*)&hp; lo = *(uint32_t*)&lp;
}

// ---------------------------------------------------------------------------
// Conversion kernels
// ---------------------------------------------------------------------------
__global__ void __launch_bounds__(256)
xcvt_kernel(const float* __restrict__ in, __half* __restrict__ outH, int n4) {
    int i = blockIdx.x * 256 + threadIdx.x;
    if (i >= n4) return;
    float4 v = ((const float4*)in)[i];
    uint2 o;
    o.x = packh2(v.x, v.y);
    o.y = packh2(v.z, v.w);
    ((uint2*)outH)[i] = o;
}

__global__ void __launch_bounds__(1024)
tsplit16_kernel(const float* __restrict__ w, __half* __restrict__ tHi,
                __half* __restrict__ tLo, int K, int N) {
    __shared__ float tile[32][33];
    int n0 = blockIdx.x * 32, k0 = blockIdx.y * 32;
    int tx = threadIdx.x & 31, ty = threadIdx.x >> 5;
    tile[ty][tx] = w[(size_t)(k0 + ty) * N + n0 + tx];
    __syncthreads();
    float v = tile[tx][ty];
    __half h = __float2half_rn(v);
    __half l = __float2half_rn(v - __half2float(h));
    size_t o = (size_t)(n0 + ty) * K + k0 + tx;
    tHi[o] = h;
    tLo[o] = l;
}

// ---------------------------------------------------------------------------
// HMMA fp16x2 GEMM: C = Ah[M,K] * (Bh+Bl)^T[N,K]
// CTA 128x128, BK=32, 256 threads, warp tile 64x32, 2-stage, 2 CTAs/SM.
// ---------------------------------------------------------------------------
#define GBK 32
#define ROWB 80
#define PLANE_B (128 * ROWB)          // 10240
#define STAGE_B (3 * PLANE_B)         // 30720
#define GEMM_SMEM (2 * STAGE_B)       // 61440

__global__ void __launch_bounds__(256, 2)
gemm_f16x2(const __half* __restrict__ Ah, const __half* __restrict__ Bh,
           const __half* __restrict__ Bl, float* __restrict__ C,
           __half* __restrict__ Chi, __half* __restrict__ Clo,
           int N, int K) {
    extern __shared__ char smem[];
    const uint32_t sb = smem_u32(smem);

    const int tid  = threadIdx.x;
    const int wid  = tid >> 5;
    const int lane = tid & 31;
    const int wm   = wid >> 2;
    const int wn   = wid & 3;
    const int bn = blockIdx.x, bm = blockIdx.y;

    const __half* aH = Ah + (size_t)(bm * 128) * K;
    const __half* bH = Bh + (size_t)(bn * 128) * K;
    const __half* bL = Bl + (size_t)(bn * 128) * K;

    const int ldRow0 = tid >> 2;
    const int ldRow1 = ldRow0 + 64;
    const int ldC8   = (tid & 3) * 8;
    const uint32_t sOff0 = (uint32_t)(ldRow0 * ROWB + ldC8 * 2);
    const uint32_t sOff1 = (uint32_t)(ldRow1 * ROWB + ldC8 * 2);

    const int aRow = wm * 64 + (lane & 15);
    const uint32_t aKB = (uint32_t)((lane >> 4) * 16);
    const int bRow = wn * 32 + ((lane >> 4) << 3) + (lane & 7);
    const uint32_t bKB = (uint32_t)(((lane >> 3) & 1) * 16);

    float acc[4][4][4];
    #pragma unroll
    for (int i = 0; i < 4; i++)
        #pragma unroll
        for (int j = 0; j < 4; j++)
            #pragma unroll
            for (int q = 0; q < 4; q++) acc[i][j][q] = 0.0f;

    const int nchunks = K / GBK;

    {
        size_t g0 = (size_t)ldRow0 * K + ldC8;
        size_t g1 = (size_t)ldRow1 * K + ldC8;
        cp_async16(sb + 0 * PLANE_B + sOff0, aH + g0);
        cp_async16(sb + 0 * PLANE_B + sOff1, aH + g1);
        cp_async16(sb + 1 * PLANE_B + sOff0, bH + g0);
        cp_async16(sb + 1 * PLANE_B + sOff1, bH + g1);
        cp_async16(sb + 2 * PLANE_B + sOff0, bL + g0);
        cp_async16(sb + 2 * PLANE_B + sOff1, bL + g1);
        cp_commit();
    }

    for (int c = 0; c < nchunks; c++) {
        const uint32_t st = sb + (uint32_t)(c & 1) * STAGE_B;
        if (c + 1 < nchunks) {
            const uint32_t st2 = sb + (uint32_t)((c + 1) & 1) * STAGE_B;
            const int k0 = (c + 1) * GBK;
            size_t g0 = (size_t)ldRow0 * K + k0 + ldC8;
            size_t g1 = (size_t)ldRow1 * K + k0 + ldC8;
            cp_async16(st2 + 0 * PLANE_B + sOff0, aH + g0);
            cp_async16(st2 + 0 * PLANE_B + sOff1, aH + g1);
            cp_async16(st2 + 1 * PLANE_B + sOff0, bH + g0);
            cp_async16(st2 + 1 * PLANE_B + sOff1, bH + g1);
            cp_async16(st2 + 2 * PLANE_B + sOff0, bL + g0);
            cp_async16(st2 + 2 * PLANE_B + sOff1, bL + g1);
            cp_commit();
            cp_wait1();
        } else {
            cp_wait0();
        }
        __syncthreads();

        #pragma unroll
        for (int kt = 0; kt < 2; kt++) {
            const uint32_t kb  = (uint32_t)(kt * 32) + aKB;
            const uint32_t kbB = (uint32_t)(kt * 32) + bKB;
            uint32_t ah[4][4];
            #pragma unroll
            for (int mt = 0; mt < 4; mt++) {
                uint32_t ro = (uint32_t)((aRow + mt * 16) * ROWB);
                ldmatrix_x4(ah[mt], st + 0 * PLANE_B + ro + kb);
            }
            uint32_t bh[2][4], bl[2][4];
            #pragma unroll
            for (int nt2 = 0; nt2 < 2; nt2++) {
                uint32_t ro = (uint32_t)((bRow + nt2 * 16) * ROWB);
                ldmatrix_x4(bh[nt2], st + 1 * PLANE_B + ro + kbB);
                ldmatrix_x4(bl[nt2], st + 2 * PLANE_B + ro + kbB);
            }
            #pragma unroll
            for (int mt = 0; mt < 4; mt++) {
                #pragma unroll
                for (int nt = 0; nt < 4; nt++) {
                    const uint32_t* bhp = &bh[nt >> 1][(nt & 1) * 2];
                    const uint32_t* blp = &bl[nt >> 1][(nt & 1) * 2];
                    mma_f16(acc[mt][nt], ah[mt], bhp, acc[mt][nt]);
                    mma_f16(acc[mt][nt], ah[mt], blp, acc[mt][nt]);
                }
            }
        }
        __syncthreads();
    }

    const int rBase = bm * 128 + wm * 64 + (lane >> 2);
    const int cBase = bn * 128 + wn * 32 + (lane & 3) * 2;
    if (Chi) {
        #pragma unroll
        for (int mt = 0; mt < 4; mt++) {
            #pragma unroll
            for (int nt = 0; nt < 4; nt++) {
                size_t i0 = (size_t)(rBase + mt * 16) * N + cBase + nt * 8;
                size_t i1 = i0 + (size_t)8 * N;
                uint32_t h0, l0, h1, l1;
                splitpack2h(acc[mt][nt][0], acc[mt][nt][1], h0, l0);
                splitpack2h(acc[mt][nt][2], acc[mt][nt][3], h1, l1);
                *(uint32_t*)(Chi + i0) = h0;
                *(uint32_t*)(Clo + i0) = l0;
                *(uint32_t*)(Chi + i1) = h1;
                *(uint32_t*)(Clo + i1) = l1;
            }
        }
    } else {
        #pragma unroll
        for (int mt = 0; mt < 4; mt++) {
            #pragma unroll
            for (int nt = 0; nt < 4; nt++) {
                float* p0 = C + (size_t)(rBase + mt * 16) * N + cBase + nt * 8;
                float* p1 = p0 + (size_t)8 * N;
                float2 v0; v0.x = acc[mt][nt][0]; v0.y = acc[mt][nt][1];
                float2 v1; v1.x = acc[mt][nt][2]; v1.y = acc[mt][nt][3];
                *(float2*)p0 = v0;
                *(float2*)p1 = v1;
            }
        }
    }
}

// ---------------------------------------------------------------------------
// HMMA flash attention (causal), fp16x2:
// S = Qh·(Kh+Kl)  (2 MMAs), O = Ph·(Vh+Vl) (2 MMAs). Q single fp16 plane.
// ---------------------------------------------------------------------------
#define FROWB 144
#define FQ_PLANE 18432
#define FKV_PLANE 9216
#define FSTAGE (4 * FKV_PLANE)
#define FLASH_SMEM (FQ_PLANE + 2 * FSTAGE)   // 92160

__global__ void __launch_bounds__(256, 1)
flash_hmma(const __half* __restrict__ qkvh, const __half* __restrict__ qkvl,
           __half* __restrict__ yh) {
    extern __shared__ char smem[];
    const uint32_t sb = smem_u32(smem);
    const int tid = threadIdx.x, wid = tid >> 5, lane = tid & 31;
    const int qt = blockIdx.x, h = blockIdx.y, b = blockIdx.z;
    const int q0 = qt * 128;
    const size_t rowB = (size_t)b * T_SEQ;
    const int ntiles = 2 * qt + 2;

    const uint32_t QHI = sb, STG0 = sb + FQ_PLANE;

    // Q loads (single fp16 plane): 1024 slots (128 rows x 8 chunks)
    #pragma unroll
    for (int i = 0; i < 4; i++) {
        int slot = tid + i * 256;
        int row = slot >> 3, ch = slot & 7;
        size_t g = (rowB + q0 + row) * N_QKV + h * HDIM + ch * 8;
        uint32_t so = (uint32_t)(row * FROWB + ch * 16);
        cp_async16(QHI + so, qkvh + g);
    }
    cp_commit();

    auto loadKV = [&](int kt, uint32_t stg) {
        const int k0 = kt * 64;
        #pragma unroll
        for (int i = 0; i < 2; i++) {
            int slot = tid + i * 256;
            int row = slot >> 3, ch = slot & 7;
            size_t g = (rowB + k0 + row) * N_QKV + h * HDIM + ch * 8;
            uint32_t so = (uint32_t)(row * FROWB + ch * 16);
            cp_async16(stg + so,                 qkvh + g + CDIM);
            cp_async16(stg + FKV_PLANE + so,     qkvl + g + CDIM);
            cp_async16(stg + 2 * FKV_PLANE + so, qkvh + g + 2 * CDIM);
            cp_async16(stg + 3 * FKV_PLANE + so, qkvl + g + 2 * CDIM);
        }
        cp_commit();
    };
    loadKV(0, STG0);
    loadKV(1, STG0 + FSTAGE);
    cp_wait1();
    __syncthreads();

    uint32_t qh[4][4];
    {
        const uint32_t ro = (uint32_t)((wid * 16 + (lane & 15)) * FROWB)
                          + (uint32_t)((lane >> 4) * 16);
        #pragma unroll
        for (int ks = 0; ks < 4; ks++)
            ldmatrix_x4(qh[ks], QHI + ro + ks * 32);
    }

    float o[8][4];
    #pragma unroll
    for (int nt = 0; nt < 8; nt++)
        #pragma unroll
        for (int j = 0; j < 4; j++) o[nt][j] = 0.0f;
    float m0 = -1e30f, m1 = -1e30f, l0 = 0.0f, l1 = 0.0f;

    const uint32_t kro = (uint32_t)((((lane >> 4) << 3) + (lane & 7)) * FROWB)
                       + (uint32_t)(((lane >> 3) & 1) * 16);
    const uint32_t vro = (uint32_t)((lane & 15) * FROWB)
                       + (uint32_t)(((lane >> 4) << 3) * 2);

    for (int kt = 0; kt < ntiles; kt++) {
        const uint32_t stg = STG0 + (uint32_t)(kt & 1) * FSTAGE;
        const int k0 = kt * 64;

        float s[8][4];
        #pragma unroll
        for (int nt = 0; nt < 8; nt++)
            #pragma unroll
            for (int j = 0; j < 4; j++) s[nt][j] = 0.0f;

        #pragma unroll
        for (int ks = 0; ks < 4; ks++) {
            uint32_t kh[4][4], kl[4][4];
            #pragma unroll
            for (int p4 = 0; p4 < 4; p4++) {
                uint32_t off = kro + (uint32_t)(p4 * 16 * FROWB) + (uint32_t)(ks * 32);
                ldmatrix_x4(kh[p4], stg + off);
                ldmatrix_x4(kl[p4], stg + FKV_PLANE + off);
            }
            #pragma unroll
            for (int nt = 0; nt < 8; nt++) {
                const uint32_t* bh = &kh[nt >> 1][(nt & 1) * 2];
                const uint32_t* bl = &kl[nt >> 1][(nt & 1) * 2];
                mma_f16(s[nt], qh[ks], bh, s[nt]);
                mma_f16(s[nt], qh[ks], bl, s[nt]);
            }
        }

        #pragma unroll
        for (int nt = 0; nt < 8; nt++)
            #pragma unroll
            for (int j = 0; j < 4; j++) s[nt][j] *= 0.125f;

        if (kt >= ntiles - 2) {
            const int qr = q0 + wid * 16 + (lane >> 2);
            const int kc = k0 + (lane & 3) * 2;
            #pragma unroll
            for (int nt = 0; nt < 8; nt++)
                #pragma unroll
                for (int j = 0; j < 4; j++)
                    if (kc + nt * 8 + (j & 1) > qr + ((j >> 1) << 3))
                        s[nt][j] = -1e30f;
        }

        float mx0 = -1e30f, mx1 = -1e30f;
        #pragma unroll
        for (int nt = 0; nt < 8; nt++) {
            mx0 = fmaxf(mx0, fmaxf(s[nt][0], s[nt][1]));
            mx1 = fmaxf(mx1, fmaxf(s[nt][2], s[nt][3]));
        }
        mx0 = fmaxf(mx0, __shfl_xor_sync(0xFFFFFFFFu, mx0, 1));
        mx0 = fmaxf(mx0, __shfl_xor_sync(0xFFFFFFFFu, mx0, 2));
        mx1 = fmaxf(mx1, __shfl_xor_sync(0xFFFFFFFFu, mx1, 1));
        mx1 = fmaxf(mx1, __shfl_xor_sync(0xFFFFFFFFu, mx1, 2));

        const float mn0 = fmaxf(m0, mx0), mn1 = fmaxf(m1, mx1);
        const float c0 = __expf(m0 - mn0), c1 = __expf(m1 - mn1);
        m0 = mn0; m1 = mn1;

        float sum0 = 0.0f, sum1 = 0.0f;
        #pragma unroll
        for (int nt = 0; nt < 8; nt++) {
            s[nt][0] = __expf(s[nt][0] - m0); sum0 += s[nt][0];
            s[nt][1] = __expf(s[nt][1] - m0); sum0 += s[nt][1];
            s[nt][2] = __expf(s[nt][2] - m1); sum1 += s[nt][2];
            s[nt][3] = __expf(s[nt][3] - m1); sum1 += s[nt][3];
        }
        sum0 += __shfl_xor_sync(0xFFFFFFFFu, sum0, 1);
        sum0 += __shfl_xor_sync(0xFFFFFFFFu, sum0, 2);
        sum1 += __shfl_xor_sync(0xFFFFFFFFu, sum1, 1);
        sum1 += __shfl_xor_sync(0xFFFFFFFFu, sum1, 2);
        l0 = l0 * c0 + sum0;
        l1 = l1 * c1 + sum1;

        #pragma unroll
        for (int nt = 0; nt < 8; nt++) {
            o[nt][0] *= c0; o[nt][1] *= c0;
            o[nt][2] *= c1; o[nt][3] *= c1;
        }

        #pragma unroll
        for (int ks = 0; ks < 4; ks++) {
            uint32_t pah[4];
            pah[0] = packh2(s[2 * ks][0],     s[2 * ks][1]);
            pah[1] = packh2(s[2 * ks][2],     s[2 * ks][3]);
            pah[2] = packh2(s[2 * ks + 1][0], s[2 * ks + 1][1]);
            pah[3] = packh2(s[2 * ks + 1][2], s[2 * ks + 1][3]);

            uint32_t vh[4][4], vl[4][4];
            #pragma unroll
            for (int p4 = 0; p4 < 4; p4++) {
                uint32_t off = vro + (uint32_t)(ks * 16 * FROWB) + (uint32_t)(p4 * 32);
                ldmatrix_x4_trans(vh[p4], stg + 2 * FKV_PLANE + off);
                ldmatrix_x4_trans(vl[p4], stg + 3 * FKV_PLANE + off);
            }
            #pragma unroll
            for (int nt = 0; nt < 8; nt++) {
                const uint32_t* bh = &vh[nt >> 1][(nt & 1) * 2];
                const uint32_t* bl = &vl[nt >> 1][(nt & 1) * 2];
                mma_f16(o[nt], pah, bh, o[nt]);
                mma_f16(o[nt], pah, bl, o[nt]);
            }
        }

        __syncthreads();
        if (kt + 2 < ntiles) loadKV(kt + 2, stg);
        if (kt + 1 < ntiles) {
            if (kt + 2 < ntiles) cp_wait1(); else cp_wait0();
            __syncthreads();
        }
    }

    const float inv0 = 1.0f / l0, inv1 = 1.0f / l1;
    const int row0 = q0 + wid * 16 + (lane >> 2);
    #pragma unroll
    for (int nt = 0; nt < 8; nt++) {
        const int col = h * HDIM + nt * 8 + (lane & 3) * 2;
        size_t i0 = (rowB + row0) * CDIM + col;
        size_t i1 = (rowB + row0 + 8) * CDIM + col;
        *(uint32_t*)(yh + i0) = packh2(o[nt][0] * inv0, o[nt][1] * inv0);
        *(uint32_t*)(yh + i1) = packh2(o[nt][2] * inv1, o[nt][3] * inv1);
    }
}

// ---------------------------------------------------------------------------
// Launch
// ---------------------------------------------------------------------------
extern "C" void kernel_launch(void* const* d_in, const int* in_sizes, int n_in,
                              void* d_out, int out_size) {
    (void)in_sizes; (void)n_in; (void)out_size;
    const float* x      = (const float*)d_in[0];
    const float* w_attn = (const float*)d_in[1];
    const float* w_proj = (const float*)d_in[2];
    float* out = (float*)d_out;

    __half *xh, *yh, *qkvh, *qkvl, *wah, *wal, *wph, *wpl;
    cudaGetSymbolAddress((void**)&xh,   g_xh);
    cudaGetSymbolAddress((void**)&qkvh, g_qkvh);
    cudaGetSymbolAddress((void**)&qkvl, g_qkvl);
    cudaGetSymbolAddress((void**)&yh,   g_yh);
    cudaGetSymbolAddress((void**)&wah,  g_wah);
    cudaGetSymbolAddress((void**)&wal,  g_wal);
    cudaGetSymbolAddress((void**)&wph,  g_wph);
    cudaGetSymbolAddress((void**)&wpl,  g_wpl);

    cudaFuncSetAttribute(gemm_f16x2, cudaFuncAttributeMaxDynamicSharedMemorySize, GEMM_SMEM);
    cudaFuncSetAttribute(flash_hmma, cudaFuncAttributeMaxDynamicSharedMemorySize, FLASH_SMEM);

    {
        int n4 = MROWS * CDIM / 4;
        xcvt_kernel<<<(n4 + 255) / 256, 256>>>(x, xh, n4);
        tsplit16_kernel<<<dim3(N_QKV / 32, CDIM / 32), 1024>>>(w_attn, wah, wal, CDIM, N_QKV);
        tsplit16_kernel<<<dim3(CDIM / 32, CDIM / 32), 1024>>>(w_proj, wph, wpl, CDIM, CDIM);
    }
    // 1) qkv = x @ w_attn  (fp16x2) -> fp16 hi/lo planes
    gemm_f16x2<<<dim3(N_QKV / 128, MROWS / 128), 256, GEMM_SMEM>>>(
        xh, wah, wal, nullptr, qkvh, qkvl, N_QKV, CDIM);
    // 2) attention (fp16x2) -> single fp16 y plane
    flash_hmma<<<dim3(T_SEQ / 128, NHEADS, BATCH), 256, FLASH_SMEM>>>(
        qkvh, qkvl, yh);
    // 3) out = y @ w_proj  (fp16x2, fp32 out)
    gemm_f16x2<<<dim3(CDIM / 128, MROWS / 128), 256, GEMM_SMEM>>>(
        yh, wph, wpl, out, nullptr, nullptr, CDIM, CDIM);
}

// round 11
// speedup vs baseline: 2.0141x; 1.3621x over previous
#include <cuda_runtime.h>
#include <cuda_bf16.h>
#include <cuda_fp16.h>
#include <cstdint>
#include <cstddef>

// Problem constants
#define BATCH   4
#define T_SEQ   2048
#define CDIM    1024
#define NHEADS  16
#define HDIM    64
#define MROWS   (BATCH * T_SEQ)        // 8192
#define N_QKV   (3 * CDIM)             // 3072

// ---------------------------------------------------------------------------
// Scratch (device globals — no runtime allocation allowed)
// ---------------------------------------------------------------------------
__device__ __align__(256) __half g_xh  [(size_t)MROWS * CDIM];
__device__ __align__(256) __half g_qkvh[(size_t)MROWS * N_QKV];
__device__ __align__(256) __half g_yh  [(size_t)MROWS * CDIM];
__device__ __align__(256) __half g_wah [(size_t)N_QKV * CDIM];
__device__ __align__(256) __half g_wph [(size_t)CDIM * CDIM];
__device__ __align__(256) __half g_wpl [(size_t)CDIM * CDIM];

// ---------------------------------------------------------------------------
// Helpers
// ---------------------------------------------------------------------------
__device__ __forceinline__ uint32_t smem_u32(const void* p) {
    uint32_t a;
    asm("{ .reg .u64 t; cvta.to.shared.u64 t, %1; cvt.u32.u64 %0, t; }"
        : "=r"(a) : "l"(p));
    return a;
}
__device__ __forceinline__ void cp_async16(uint32_t saddr, const void* gaddr) {
    asm volatile("cp.async.ca.shared.global [%0], [%1], 16;"
                 :: "r"(saddr), "l"(gaddr));
}
__device__ __forceinline__ void cp_commit() { asm volatile("cp.async.commit_group;"); }
__device__ __forceinline__ void cp_wait1()  { asm volatile("cp.async.wait_group 1;"); }
__device__ __forceinline__ void cp_wait0()  { asm volatile("cp.async.wait_group 0;"); }

__device__ __forceinline__ void ldmatrix_x4(uint32_t* r, uint32_t addr) {
    asm volatile("ldmatrix.sync.aligned.m8n8.x4.shared.b16 {%0,%1,%2,%3}, [%4];"
                 : "=r"(r[0]), "=r"(r[1]), "=r"(r[2]), "=r"(r[3]) : "r"(addr));
}
__device__ __forceinline__ void ldmatrix_x4_trans(uint32_t* r, uint32_t addr) {
    asm volatile("ldmatrix.sync.aligned.m8n8.x4.trans.shared.b16 {%0,%1,%2,%3}, [%4];"
                 : "=r"(r[0]), "=r"(r[1]), "=r"(r[2]), "=r"(r[3]) : "r"(addr));
}
__device__ __forceinline__ void mma_f16(float* d, const uint32_t* a,
                                        const uint32_t* b, const float* c) {
    asm volatile(
        "mma.sync.aligned.m16n8k16.row.col.f32.f16.f16.f32 "
        "{%0,%1,%2,%3}, {%4,%5,%6,%7}, {%8,%9}, {%10,%11,%12,%13};"
        : "=f"(d[0]), "=f"(d[1]), "=f"(d[2]), "=f"(d[3])
        : "r"(a[0]), "r"(a[1]), "r"(a[2]), "r"(a[3]),
          "r"(b[0]), "r"(b[1]),
          "f"(c[0]), "f"(c[1]), "f"(c[2]), "f"(c[3]));
}
__device__ __forceinline__ uint32_t packh2(float x, float y) {
    __half2 p;
    p.x = __float2half_rn(x); p.y = __float2half_rn(y);
    return *(uint32_t*)&p;
}

// ---------------------------------------------------------------------------
// Conversion kernels
// ---------------------------------------------------------------------------
__global__ void __launch_bounds__(256)
xcvt_kernel(const float* __restrict__ in, __half* __restrict__ outH, int n4) {
    int i = blockIdx.x * 256 + threadIdx.x;
    if (i >= n4) return;
    float4 v = ((const float4*)in)[i];
    uint2 o;
    o.x = packh2(v.x, v.y);
    o.y = packh2(v.z, v.w);
    ((uint2*)outH)[i] = o;
}

// Transpose (hi only): w[K,N] fp32 -> wT [N,K] half
__global__ void __launch_bounds__(1024)
t16_kernel(const float* __restrict__ w, __half* __restrict__ tHi, int K, int N) {
    __shared__ float tile[32][33];
    int n0 = blockIdx.x * 32, k0 = blockIdx.y * 32;
    int tx = threadIdx.x & 31, ty = threadIdx.x >> 5;
    tile[ty][tx] = w[(size_t)(k0 + ty) * N + n0 + tx];
    __syncthreads();
    tHi[(size_t)(n0 + ty) * K + k0 + tx] = __float2half_rn(tile[tx][ty]);
}

// Transpose + hi/lo split: w[K,N] fp32 -> wT hi/lo [N,K] half
__global__ void __launch_bounds__(1024)
tsplit16_kernel(const float* __restrict__ w, __half* __restrict__ tHi,
                __half* __restrict__ tLo, int K, int N) {
    __shared__ float tile[32][33];
    int n0 = blockIdx.x * 32, k0 = blockIdx.y * 32;
    int tx = threadIdx.x & 31, ty = threadIdx.x >> 5;
    tile[ty][tx] = w[(size_t)(k0 + ty) * N + n0 + tx];
    __syncthreads();
    float v = tile[tx][ty];
    __half h = __float2half_rn(v);
    __half l = __float2half_rn(v - __half2float(h));
    size_t o = (size_t)(n0 + ty) * K + k0 + tx;
    tHi[o] = h;
    tLo[o] = l;
}

// ---------------------------------------------------------------------------
// HMMA fp16 GEMM, templated on dual-B correction plane.
// C = Ah[M,K] * (Bh[+Bl])^T[N,K]
// CTA 128x128, BK=32, 256 threads, warp tile 64x32, 2-stage, 2 CTAs/SM.
// Output: fp32 C (if C != null) else single fp16 plane Ch.
// ---------------------------------------------------------------------------
#define GBK 32
#define ROWB 80
#define PLANE_B (128 * ROWB)                   // 10240
#define GEMM_SMEM_MAX (2 * 3 * PLANE_B)        // dual-B stage x2 = 61440

template <bool DUALB>
__global__ void __launch_bounds__(256, 2)
gemm_f16(const __half* __restrict__ Ah, const __half* __restrict__ Bh,
         const __half* __restrict__ Bl, float* __restrict__ C,
         __half* __restrict__ Ch, int N, int K) {
    constexpr uint32_t STAGE = (DUALB ? 3 : 2) * PLANE_B;
    extern __shared__ char smem[];
    const uint32_t sb = smem_u32(smem);

    const int tid  = threadIdx.x;
    const int wid  = tid >> 5;
    const int lane = tid & 31;
    const int wm   = wid >> 2;
    const int wn   = wid & 3;
    const int bn = blockIdx.x, bm = blockIdx.y;

    const __half* aH = Ah + (size_t)(bm * 128) * K;
    const __half* bH = Bh + (size_t)(bn * 128) * K;
    const __half* bL = DUALB ? (Bl + (size_t)(bn * 128) * K) : nullptr;

    const int ldRow0 = tid >> 2;
    const int ldRow1 = ldRow0 + 64;
    const int ldC8   = (tid & 3) * 8;
    const uint32_t sOff0 = (uint32_t)(ldRow0 * ROWB + ldC8 * 2);
    const uint32_t sOff1 = (uint32_t)(ldRow1 * ROWB + ldC8 * 2);

    const int aRow = wm * 64 + (lane & 15);
    const uint32_t aKB = (uint32_t)((lane >> 4) * 16);
    const int bRow = wn * 32 + ((lane >> 4) << 3) + (lane & 7);
    const uint32_t bKB = (uint32_t)(((lane >> 3) & 1) * 16);

    float acc[4][4][4];
    #pragma unroll
    for (int i = 0; i < 4; i++)
        #pragma unroll
        for (int j = 0; j < 4; j++)
            #pragma unroll
            for (int q = 0; q < 4; q++) acc[i][j][q] = 0.0f;

    const int nchunks = K / GBK;

    auto loadChunk = [&](int c) {
        const uint32_t st = sb + (uint32_t)(c & 1) * STAGE;
        const int k0 = c * GBK;
        size_t g0 = (size_t)ldRow0 * K + k0 + ldC8;
        size_t g1 = (size_t)ldRow1 * K + k0 + ldC8;
        cp_async16(st + 0 * PLANE_B + sOff0, aH + g0);
        cp_async16(st + 0 * PLANE_B + sOff1, aH + g1);
        cp_async16(st + 1 * PLANE_B + sOff0, bH + g0);
        cp_async16(st + 1 * PLANE_B + sOff1, bH + g1);
        if (DUALB) {
            cp_async16(st + 2 * PLANE_B + sOff0, bL + g0);
            cp_async16(st + 2 * PLANE_B + sOff1, bL + g1);
        }
        cp_commit();
    };

    loadChunk(0);

    for (int c = 0; c < nchunks; c++) {
        const uint32_t st = sb + (uint32_t)(c & 1) * STAGE;
        if (c + 1 < nchunks) {
            loadChunk(c + 1);
            cp_wait1();
        } else {
            cp_wait0();
        }
        __syncthreads();

        #pragma unroll
        for (int kt = 0; kt < 2; kt++) {
            const uint32_t kb  = (uint32_t)(kt * 32) + aKB;
            const uint32_t kbB = (uint32_t)(kt * 32) + bKB;
            uint32_t ah[4][4];
            #pragma unroll
            for (int mt = 0; mt < 4; mt++) {
                uint32_t ro = (uint32_t)((aRow + mt * 16) * ROWB);
                ldmatrix_x4(ah[mt], st + 0 * PLANE_B + ro + kb);
            }
            uint32_t bh[2][4], bl[2][4];
            #pragma unroll
            for (int nt2 = 0; nt2 < 2; nt2++) {
                uint32_t ro = (uint32_t)((bRow + nt2 * 16) * ROWB);
                ldmatrix_x4(bh[nt2], st + 1 * PLANE_B + ro + kbB);
                if (DUALB) ldmatrix_x4(bl[nt2], st + 2 * PLANE_B + ro + kbB);
            }
            #pragma unroll
            for (int mt = 0; mt < 4; mt++) {
                #pragma unroll
                for (int nt = 0; nt < 4; nt++) {
                    const uint32_t* bhp = &bh[nt >> 1][(nt & 1) * 2];
                    mma_f16(acc[mt][nt], ah[mt], bhp, acc[mt][nt]);
                    if (DUALB) {
                        const uint32_t* blp = &bl[nt >> 1][(nt & 1) * 2];
                        mma_f16(acc[mt][nt], ah[mt], blp, acc[mt][nt]);
                    }
                }
            }
        }
        __syncthreads();
    }

    const int rBase = bm * 128 + wm * 64 + (lane >> 2);
    const int cBase = bn * 128 + wn * 32 + (lane & 3) * 2;
    if (C) {
        #pragma unroll
        for (int mt = 0; mt < 4; mt++) {
            #pragma unroll
            for (int nt = 0; nt < 4; nt++) {
                float* p0 = C + (size_t)(rBase + mt * 16) * N + cBase + nt * 8;
                float* p1 = p0 + (size_t)8 * N;
                float2 v0; v0.x = acc[mt][nt][0]; v0.y = acc[mt][nt][1];
                float2 v1; v1.x = acc[mt][nt][2]; v1.y = acc[mt][nt][3];
                *(float2*)p0 = v0;
                *(float2*)p1 = v1;
            }
        }
    } else {
        #pragma unroll
        for (int mt = 0; mt < 4; mt++) {
            #pragma unroll
            for (int nt = 0; nt < 4; nt++) {
                size_t i0 = (size_t)(rBase + mt * 16) * N + cBase + nt * 8;
                size_t i1 = i0 + (size_t)8 * N;
                *(uint32_t*)(Ch + i0) = packh2(acc[mt][nt][0], acc[mt][nt][1]);
                *(uint32_t*)(Ch + i1) = packh2(acc[mt][nt][2], acc[mt][nt][3]);
            }
        }
    }
}

// ---------------------------------------------------------------------------
// HMMA flash attention (causal), pure fp16 single-plane:
// S = Qh·Kh (1 MMA), O = Ph·Vh (1 MMA).
// ---------------------------------------------------------------------------
#define FROWB 144
#define FQ_PLANE 18432
#define FKV_PLANE 9216
#define FSTAGE (2 * FKV_PLANE)                  // 18432
#define FLASH_SMEM (FQ_PLANE + 2 * FSTAGE)      // 55296

__global__ void __launch_bounds__(256, 1)
flash_hmma(const __half* __restrict__ qkvh, __half* __restrict__ yh) {
    extern __shared__ char smem[];
    const uint32_t sb = smem_u32(smem);
    const int tid = threadIdx.x, wid = tid >> 5, lane = tid & 31;
    const int qt = blockIdx.x, h = blockIdx.y, b = blockIdx.z;
    const int q0 = qt * 128;
    const size_t rowB = (size_t)b * T_SEQ;
    const int ntiles = 2 * qt + 2;

    const uint32_t QHI = sb, STG0 = sb + FQ_PLANE;

    #pragma unroll
    for (int i = 0; i < 4; i++) {
        int slot = tid + i * 256;
        int row = slot >> 3, ch = slot & 7;
        size_t g = (rowB + q0 + row) * N_QKV + h * HDIM + ch * 8;
        uint32_t so = (uint32_t)(row * FROWB + ch * 16);
        cp_async16(QHI + so, qkvh + g);
    }
    cp_commit();

    auto loadKV = [&](int kt, uint32_t stg) {
        const int k0 = kt * 64;
        #pragma unroll
        for (int i = 0; i < 2; i++) {
            int slot = tid + i * 256;
            int row = slot >> 3, ch = slot & 7;
            size_t g = (rowB + k0 + row) * N_QKV + h * HDIM + ch * 8;
            uint32_t so = (uint32_t)(row * FROWB + ch * 16);
            cp_async16(stg + so,             qkvh + g + CDIM);        // K
            cp_async16(stg + FKV_PLANE + so, qkvh + g + 2 * CDIM);    // V
        }
        cp_commit();
    };
    loadKV(0, STG0);
    loadKV(1, STG0 + FSTAGE);
    cp_wait1();
    __syncthreads();

    uint32_t qh[4][4];
    {
        const uint32_t ro = (uint32_t)((wid * 16 + (lane & 15)) * FROWB)
                          + (uint32_t)((lane >> 4) * 16);
        #pragma unroll
        for (int ks = 0; ks < 4; ks++)
            ldmatrix_x4(qh[ks], QHI + ro + ks * 32);
    }

    float o[8][4];
    #pragma unroll
    for (int nt = 0; nt < 8; nt++)
        #pragma unroll
        for (int j = 0; j < 4; j++) o[nt][j] = 0.0f;
    float m0 = -1e30f, m1 = -1e30f, l0 = 0.0f, l1 = 0.0f;

    const uint32_t kro = (uint32_t)((((lane >> 4) << 3) + (lane & 7)) * FROWB)
                       + (uint32_t)(((lane >> 3) & 1) * 16);
    const uint32_t vro = (uint32_t)((lane & 15) * FROWB)
                       + (uint32_t)(((lane >> 4) << 3) * 2);

    for (int kt = 0; kt < ntiles; kt++) {
        const uint32_t stg = STG0 + (uint32_t)(kt & 1) * FSTAGE;
        const int k0 = kt * 64;

        float s[8][4];
        #pragma unroll
        for (int nt = 0; nt < 8; nt++)
            #pragma unroll
            for (int j = 0; j < 4; j++) s[nt][j] = 0.0f;

        #pragma unroll
        for (int ks = 0; ks < 4; ks++) {
            uint32_t kh[4][4];
            #pragma unroll
            for (int p4 = 0; p4 < 4; p4++) {
                uint32_t off = kro + (uint32_t)(p4 * 16 * FROWB) + (uint32_t)(ks * 32);
                ldmatrix_x4(kh[p4], stg + off);
            }
            #pragma unroll
            for (int nt = 0; nt < 8; nt++) {
                const uint32_t* bh = &kh[nt >> 1][(nt & 1) * 2];
                mma_f16(s[nt], qh[ks], bh, s[nt]);
            }
        }

        #pragma unroll
        for (int nt = 0; nt < 8; nt++)
            #pragma unroll
            for (int j = 0; j < 4; j++) s[nt][j] *= 0.125f;

        if (kt >= ntiles - 2) {
            const int qr = q0 + wid * 16 + (lane >> 2);
            const int kc = k0 + (lane & 3) * 2;
            #pragma unroll
            for (int nt = 0; nt < 8; nt++)
                #pragma unroll
                for (int j = 0; j < 4; j++)
                    if (kc + nt * 8 + (j & 1) > qr + ((j >> 1) << 3))
                        s[nt][j] = -1e30f;
        }

        float mx0 = -1e30f, mx1 = -1e30f;
        #pragma unroll
        for (int nt = 0; nt < 8; nt++) {
            mx0 = fmaxf(mx0, fmaxf(s[nt][0], s[nt][1]));
            mx1 = fmaxf(mx1, fmaxf(s[nt][2], s[nt][3]));
        }
        mx0 = fmaxf(mx0, __shfl_xor_sync(0xFFFFFFFFu, mx0, 1));
        mx0 = fmaxf(mx0, __shfl_xor_sync(0xFFFFFFFFu, mx0, 2));
        mx1 = fmaxf(mx1, __shfl_xor_sync(0xFFFFFFFFu, mx1, 1));
        mx1 = fmaxf(mx1, __shfl_xor_sync(0xFFFFFFFFu, mx1, 2));

        const float mn0 = fmaxf(m0, mx0), mn1 = fmaxf(m1, mx1);
        const float c0 = __expf(m0 - mn0), c1 = __expf(m1 - mn1);
        m0 = mn0; m1 = mn1;

        float sum0 = 0.0f, sum1 = 0.0f;
        #pragma unroll
        for (int nt = 0; nt < 8; nt++) {
            s[nt][0] = __expf(s[nt][0] - m0); sum0 += s[nt][0];
            s[nt][1] = __expf(s[nt][1] - m0); sum0 += s[nt][1];
            s[nt][2] = __expf(s[nt][2] - m1); sum1 += s[nt][2];
            s[nt][3] = __expf(s[nt][3] - m1); sum1 += s[nt][3];
        }
        sum0 += __shfl_xor_sync(0xFFFFFFFFu, sum0, 1);
        sum0 += __shfl_xor_sync(0xFFFFFFFFu, sum0, 2);
        sum1 += __shfl_xor_sync(0xFFFFFFFFu, sum1, 1);
        sum1 += __shfl_xor_sync(0xFFFFFFFFu, sum1, 2);
        l0 = l0 * c0 + sum0;
        l1 = l1 * c1 + sum1;

        #pragma unroll
        for (int nt = 0; nt < 8; nt++) {
            o[nt][0] *= c0; o[nt][1] *= c0;
            o[nt][2] *= c1; o[nt][3] *= c1;
        }

        #pragma unroll
        for (int ks = 0; ks < 4; ks++) {
            uint32_t pah[4];
            pah[0] = packh2(s[2 * ks][0],     s[2 * ks][1]);
            pah[1] = packh2(s[2 * ks][2],     s[2 * ks][3]);
            pah[2] = packh2(s[2 * ks + 1][0], s[2 * ks + 1][1]);
            pah[3] = packh2(s[2 * ks + 1][2], s[2 * ks + 1][3]);

            uint32_t vh[4][4];
            #pragma unroll
            for (int p4 = 0; p4 < 4; p4++) {
                uint32_t off = vro + (uint32_t)(ks * 16 * FROWB) + (uint32_t)(p4 * 32);
                ldmatrix_x4_trans(vh[p4], stg + FKV_PLANE + off);
            }
            #pragma unroll
            for (int nt = 0; nt < 8; nt++) {
                const uint32_t* bh = &vh[nt >> 1][(nt & 1) * 2];
                mma_f16(o[nt], pah, bh, o[nt]);
            }
        }

        __syncthreads();
        if (kt + 2 < ntiles) loadKV(kt + 2, stg);
        if (kt + 1 < ntiles) {
            if (kt + 2 < ntiles) cp_wait1(); else cp_wait0();
            __syncthreads();
        }
    }

    const float inv0 = 1.0f / l0, inv1 = 1.0f / l1;
    const int row0 = q0 + wid * 16 + (lane >> 2);
    #pragma unroll
    for (int nt = 0; nt < 8; nt++) {
        const int col = h * HDIM + nt * 8 + (lane & 3) * 2;
        size_t i0 = (rowB + row0) * CDIM + col;
        size_t i1 = (rowB + row0 + 8) * CDIM + col;
        *(uint32_t*)(yh + i0) = packh2(o[nt][0] * inv0, o[nt][1] * inv0);
        *(uint32_t*)(yh + i1) = packh2(o[nt][2] * inv1, o[nt][3] * inv1);
    }
}

// ---------------------------------------------------------------------------
// Launch
// ---------------------------------------------------------------------------
extern "C" void kernel_launch(void* const* d_in, const int* in_sizes, int n_in,
                              void* d_out, int out_size) {
    (void)in_sizes; (void)n_in; (void)out_size;
    const float* x      = (const float*)d_in[0];
    const float* w_attn = (const float*)d_in[1];
    const float* w_proj = (const float*)d_in[2];
    float* out = (float*)d_out;

    __half *xh, *yh, *qkvh, *wah, *wph, *wpl;
    cudaGetSymbolAddress((void**)&xh,   g_xh);
    cudaGetSymbolAddress((void**)&qkvh, g_qkvh);
    cudaGetSymbolAddress((void**)&yh,   g_yh);
    cudaGetSymbolAddress((void**)&wah,  g_wah);
    cudaGetSymbolAddress((void**)&wph,  g_wph);
    cudaGetSymbolAddress((void**)&wpl,  g_wpl);

    cudaFuncSetAttribute(gemm_f16<false>, cudaFuncAttributeMaxDynamicSharedMemorySize, GEMM_SMEM_MAX);
    cudaFuncSetAttribute(gemm_f16<true>,  cudaFuncAttributeMaxDynamicSharedMemorySize, GEMM_SMEM_MAX);
    cudaFuncSetAttribute(flash_hmma,      cudaFuncAttributeMaxDynamicSharedMemorySize, FLASH_SMEM);

    {
        int n4 = MROWS * CDIM / 4;
        xcvt_kernel<<<(n4 + 255) / 256, 256>>>(x, xh, n4);
        t16_kernel<<<dim3(N_QKV / 32, CDIM / 32), 1024>>>(w_attn, wah, CDIM, N_QKV);
        tsplit16_kernel<<<dim3(CDIM / 32, CDIM / 32), 1024>>>(w_proj, wph, wpl, CDIM, CDIM);
    }
    // 1) qkv = x @ w_attn   (pure fp16, single B plane) -> fp16 qkv
    gemm_f16<false><<<dim3(N_QKV / 128, MROWS / 128), 256, 2 * 2 * PLANE_B>>>(
        xh, wah, nullptr, nullptr, qkvh, N_QKV, CDIM);
    // 2) attention (pure fp16) -> fp16 y
    flash_hmma<<<dim3(T_SEQ / 128, NHEADS, BATCH), 256, FLASH_SMEM>>>(qkvh, yh);
    // 3) out = y @ w_proj   (fp16x2 on weights — accuracy hedge, fp32 out)
    gemm_f16<true><<<dim3(CDIM / 128, MROWS / 128), 256, 2 * 3 * PLANE_B>>>(
        yh, wph, wpl, out, nullptr, CDIM, CDIM);
}